// round 3
// baseline (speedup 1.0000x reference)
#include <cuda_runtime.h>
#include <math_constants.h>

// Single-query attention: y = softmax(K @ q) @ V
//   q: [256] f32, K: [131072, 256] f32, V: [131072, 256] f32 -> y: [256] f32
// Fully fused single kernel. Pass1 (HBM-roofline streaming, measured 8.4TB/s)
// + two-level "last-arriver combines" tree (no spin, no extra launches).
// Final combiner resets counters so graph replays stay deterministic.

#define M_TOTAL   131072
#define DIM       256
#define NUM_CTAS  1024
#define ROWS_PER_CTA (M_TOTAL / NUM_CTAS)     // 128
#define NWARPS    8
#define ROWS_PER_WARP (ROWS_PER_CTA / NWARPS) // 16

#define NGROUPS   32
#define GROUP_SZ  (NUM_CTAS / NGROUPS)        // 32

// Scratch (allocation-free): ~1.1 MB
__device__ float g_part[NUM_CTAS][DIM];
__device__ float g_m[NUM_CTAS];
__device__ float g_l[NUM_CTAS];
__device__ float g_part2[NGROUPS][DIM];
__device__ float g_m2[NGROUPS];
__device__ float g_l2[NGROUPS];
__device__ unsigned int g_cnt1[NGROUPS];  // zero-init; reset by final combiner
__device__ unsigned int g_cnt2;

__global__ __launch_bounds__(256)
void sqa_fused(const float* __restrict__ q,
               const float* __restrict__ K,
               const float* __restrict__ V,
               float* __restrict__ out) {
    const int tid  = threadIdx.x;
    const int warp = tid >> 5;
    const int lane = tid & 31;
    const int bid  = blockIdx.x;

    // ---------------- Pass 1: stream 128 KV rows, online softmax ----------
    const float4 q0 = reinterpret_cast<const float4*>(q)[lane];
    const float4 q1 = reinterpret_cast<const float4*>(q)[lane + 32];

    const int row0 = bid * ROWS_PER_CTA + warp * ROWS_PER_WARP;

    float m = -CUDART_INF_F;
    float l = 0.0f;
    float4 a0 = make_float4(0.f, 0.f, 0.f, 0.f);
    float4 a1 = make_float4(0.f, 0.f, 0.f, 0.f);

    #pragma unroll 2
    for (int r = 0; r < ROWS_PER_WARP; ++r) {
        const size_t row = (size_t)(row0 + r);
        const float4* Kr = reinterpret_cast<const float4*>(K + row * DIM);
        const float4* Vr = reinterpret_cast<const float4*>(V + row * DIM);

        const float4 k0 = Kr[lane];
        const float4 k1 = Kr[lane + 32];
        const float4 v0 = Vr[lane];
        const float4 v1 = Vr[lane + 32];

        float d = k0.x * q0.x + k0.y * q0.y + k0.z * q0.z + k0.w * q0.w
                + k1.x * q1.x + k1.y * q1.y + k1.z * q1.z + k1.w * q1.w;
        #pragma unroll
        for (int off = 16; off > 0; off >>= 1)
            d += __shfl_xor_sync(0xffffffffu, d, off);

        const float mnew  = fmaxf(m, d);
        const float scale = __expf(m - mnew);   // exp(-inf)=0 on first iter
        const float w     = __expf(d - mnew);
        l = l * scale + w;
        a0.x = a0.x * scale + w * v0.x;
        a0.y = a0.y * scale + w * v0.y;
        a0.z = a0.z * scale + w * v0.z;
        a0.w = a0.w * scale + w * v0.w;
        a1.x = a1.x * scale + w * v1.x;
        a1.y = a1.y * scale + w * v1.y;
        a1.z = a1.z * scale + w * v1.z;
        a1.w = a1.w * scale + w * v1.w;
        m = mnew;
    }

    // Merge 8 warps within the CTA
    __shared__ float s_m[NWARPS];
    __shared__ float s_l[NWARPS];
    __shared__ float s_acc[NWARPS][DIM];
    __shared__ unsigned int s_last;

    if (lane == 0) { s_m[warp] = m; s_l[warp] = l; }
    float* dst = s_acc[warp];
    dst[lane * 4 + 0]       = a0.x;
    dst[lane * 4 + 1]       = a0.y;
    dst[lane * 4 + 2]       = a0.z;
    dst[lane * 4 + 3]       = a0.w;
    dst[128 + lane * 4 + 0] = a1.x;
    dst[128 + lane * 4 + 1] = a1.y;
    dst[128 + lane * 4 + 2] = a1.z;
    dst[128 + lane * 4 + 3] = a1.w;
    __syncthreads();

    float bm = s_m[0];
    #pragma unroll
    for (int w2 = 1; w2 < NWARPS; ++w2) bm = fmaxf(bm, s_m[w2]);

    float y = 0.0f;
    float L = 0.0f;
    #pragma unroll
    for (int w2 = 0; w2 < NWARPS; ++w2) {
        const float sf = __expf(s_m[w2] - bm);
        y += s_acc[w2][tid] * sf;
        L += s_l[w2] * sf;
    }

    g_part[bid][tid] = y;
    if (tid == 0) { g_m[bid] = bm; g_l[bid] = L; }

    // ---------------- Level 1: last CTA of each group combines ------------
    const int grp = bid / GROUP_SZ;
    __threadfence();
    if (tid == 0)
        s_last = (atomicAdd(&g_cnt1[grp], 1u) == GROUP_SZ - 1u);
    __syncthreads();
    if (!s_last) return;
    __threadfence();  // acquire: others' writes visible

    {
        const int i0 = grp * GROUP_SZ;
        float gm = g_m[i0];
        #pragma unroll
        for (int j = 1; j < GROUP_SZ; ++j) gm = fmaxf(gm, g_m[i0 + j]);

        float acc = 0.0f;
        float ll  = 0.0f;
        #pragma unroll 4
        for (int j = 0; j < GROUP_SZ; ++j) {
            const float sf = __expf(g_m[i0 + j] - gm);
            acc += g_part[i0 + j][tid] * sf;
            ll  += g_l[i0 + j] * sf;
        }
        g_part2[grp][tid] = acc;
        if (tid == 0) { g_m2[grp] = gm; g_l2[grp] = ll; }
    }

    // ---------------- Level 2: last group-combiner does final -------------
    __threadfence();
    __syncthreads();
    if (tid == 0)
        s_last = (atomicAdd(&g_cnt2, 1u) == NGROUPS - 1u);
    __syncthreads();
    if (!s_last) return;
    __threadfence();

    {
        float gm = g_m2[0];
        #pragma unroll
        for (int j = 1; j < NGROUPS; ++j) gm = fmaxf(gm, g_m2[j]);

        float acc = 0.0f;
        float ll  = 0.0f;
        #pragma unroll 4
        for (int j = 0; j < NGROUPS; ++j) {
            const float sf = __expf(g_m2[j] - gm);
            acc += g_part2[j][tid] * sf;
            ll  += g_l2[j] * sf;
        }
        out[tid] = acc / ll;
    }

    // Reset counters for next graph replay (only this CTA is alive here).
    if (tid < NGROUPS) g_cnt1[tid] = 0u;
    if (tid == 0) g_cnt2 = 0u;
}

extern "C" void kernel_launch(void* const* d_in, const int* in_sizes, int n_in,
                              void* d_out, int out_size) {
    const float* q = (const float*)d_in[0];
    const float* K = (const float*)d_in[1];
    const float* V = (const float*)d_in[2];
    float* out = (float*)d_out;

    sqa_fused<<<NUM_CTAS, 256>>>(q, K, V, out);
}

// round 4
// speedup vs baseline: 1.3020x; 1.3020x over previous
#include <cuda_runtime.h>
#include <math_constants.h>

// Single-query attention: y = softmax(K @ q) @ V   (fp32, M=131072, D=256)
// Single fused kernel. Pass1 restructured into two latency-tolerant phases
// (batched K loads -> logits in regs; then batched V loads -> weighted acc)
// so MLP does not depend on compiler scheduling around a serial softmax chain.
// Combine via two-level last-arriver tree; final CTA resets counters.

#define M_TOTAL   131072
#define DIM       256
#define NUM_CTAS  1024
#define ROWS_PER_CTA (M_TOTAL / NUM_CTAS)     // 128
#define NWARPS    8
#define ROWS_PER_WARP (ROWS_PER_CTA / NWARPS) // 16
#define RB        4                            // row batch

#define NGROUPS   32
#define GROUP_SZ  (NUM_CTAS / NGROUPS)        // 32

// Scratch (allocation-free): ~1.1 MB
__device__ float g_part[NUM_CTAS][DIM];
__device__ float g_m[NUM_CTAS];
__device__ float g_l[NUM_CTAS];
__device__ float g_part2[NGROUPS][DIM];
__device__ float g_m2[NGROUPS];
__device__ float g_l2[NGROUPS];
__device__ unsigned int g_cnt1[NGROUPS];  // zero-init; reset by final combiner
__device__ unsigned int g_cnt2;

__global__ __launch_bounds__(256)
void sqa_fused(const float* __restrict__ q,
               const float* __restrict__ K,
               const float* __restrict__ V,
               float* __restrict__ out) {
    const int tid  = threadIdx.x;
    const int warp = tid >> 5;
    const int lane = tid & 31;
    const int bid  = blockIdx.x;

    const float4 q0 = reinterpret_cast<const float4*>(q)[lane];
    const float4 q1 = reinterpret_cast<const float4*>(q)[lane + 32];

    const int row0 = bid * ROWS_PER_CTA + warp * ROWS_PER_WARP;

    // ---------------- Phase A: K stream -> 16 logits in registers ---------
    float d[ROWS_PER_WARP];

    #pragma unroll
    for (int rb = 0; rb < ROWS_PER_WARP; rb += RB) {
        float4 k0[RB], k1[RB];
        // front-batched loads: 8 independent LDG.128
        #pragma unroll
        for (int j = 0; j < RB; ++j) {
            const float4* Kr =
                reinterpret_cast<const float4*>(K + (size_t)(row0 + rb + j) * DIM);
            k0[j] = Kr[lane];
            k1[j] = Kr[lane + 32];
        }
        #pragma unroll
        for (int j = 0; j < RB; ++j) {
            float v = k0[j].x * q0.x + k0[j].y * q0.y + k0[j].z * q0.z + k0[j].w * q0.w
                    + k1[j].x * q1.x + k1[j].y * q1.y + k1[j].z * q1.z + k1[j].w * q1.w;
            #pragma unroll
            for (int off = 16; off > 0; off >>= 1)
                v += __shfl_xor_sync(0xffffffffu, v, off);
            d[rb + j] = v;
        }
    }

    // max / weights / l (no serial dependence in the load loops above)
    float m = d[0];
    #pragma unroll
    for (int r = 1; r < ROWS_PER_WARP; ++r) m = fmaxf(m, d[r]);
    float w[ROWS_PER_WARP];
    float l = 0.0f;
    #pragma unroll
    for (int r = 0; r < ROWS_PER_WARP; ++r) { w[r] = __expf(d[r] - m); l += w[r]; }

    // ---------------- Phase B: V stream -> weighted accumulation ----------
    float4 a0 = make_float4(0.f, 0.f, 0.f, 0.f);
    float4 a1 = make_float4(0.f, 0.f, 0.f, 0.f);

    #pragma unroll
    for (int rb = 0; rb < ROWS_PER_WARP; rb += RB) {
        float4 v0[RB], v1[RB];
        #pragma unroll
        for (int j = 0; j < RB; ++j) {
            const float4* Vr =
                reinterpret_cast<const float4*>(V + (size_t)(row0 + rb + j) * DIM);
            v0[j] = Vr[lane];
            v1[j] = Vr[lane + 32];
        }
        #pragma unroll
        for (int j = 0; j < RB; ++j) {
            const float wj = w[rb + j];
            a0.x += wj * v0[j].x;  a0.y += wj * v0[j].y;
            a0.z += wj * v0[j].z;  a0.w += wj * v0[j].w;
            a1.x += wj * v1[j].x;  a1.y += wj * v1[j].y;
            a1.z += wj * v1[j].z;  a1.w += wj * v1[j].w;
        }
    }

    // ---------------- Merge 8 warps within the CTA ------------------------
    __shared__ float s_m[NWARPS];
    __shared__ float s_l[NWARPS];
    __shared__ float s_acc[NWARPS][DIM];
    __shared__ unsigned int s_last;

    if (lane == 0) { s_m[warp] = m; s_l[warp] = l; }
    float* dst = s_acc[warp];
    dst[lane * 4 + 0]       = a0.x;
    dst[lane * 4 + 1]       = a0.y;
    dst[lane * 4 + 2]       = a0.z;
    dst[lane * 4 + 3]       = a0.w;
    dst[128 + lane * 4 + 0] = a1.x;
    dst[128 + lane * 4 + 1] = a1.y;
    dst[128 + lane * 4 + 2] = a1.z;
    dst[128 + lane * 4 + 3] = a1.w;
    __syncthreads();

    float bm = s_m[0];
    #pragma unroll
    for (int w2 = 1; w2 < NWARPS; ++w2) bm = fmaxf(bm, s_m[w2]);

    float y = 0.0f;
    float L = 0.0f;
    #pragma unroll
    for (int w2 = 0; w2 < NWARPS; ++w2) {
        const float sf = __expf(s_m[w2] - bm);
        y += s_acc[w2][tid] * sf;
        L += s_l[w2] * sf;
    }

    g_part[bid][tid] = y;
    if (tid == 0) { g_m[bid] = bm; g_l[bid] = L; }

    // ---------------- Level 1: last CTA of each group combines ------------
    const int grp = bid / GROUP_SZ;
    __syncthreads();  // all stores above done (smem-ordered; g_part stores issued)
    if (tid == 0) {
        __threadfence();  // release: publish this CTA's global stores
        s_last = (atomicAdd(&g_cnt1[grp], 1u) == GROUP_SZ - 1u);
    }
    __syncthreads();
    if (!s_last) return;
    if (tid == 0) __threadfence();  // acquire
    __syncthreads();

    {
        const int i0 = grp * GROUP_SZ;
        float gm = g_m[i0];
        #pragma unroll
        for (int j = 1; j < GROUP_SZ; ++j) gm = fmaxf(gm, g_m[i0 + j]);

        float acc = 0.0f;
        float ll  = 0.0f;
        #pragma unroll 4
        for (int j = 0; j < GROUP_SZ; ++j) {
            const float sf = __expf(g_m[i0 + j] - gm);
            acc += g_part[i0 + j][tid] * sf;
            ll  += g_l[i0 + j] * sf;
        }
        g_part2[grp][tid] = acc;
        if (tid == 0) { g_m2[grp] = gm; g_l2[grp] = ll; }
    }

    // ---------------- Level 2: last group-combiner does final -------------
    __syncthreads();
    if (tid == 0) {
        __threadfence();
        s_last = (atomicAdd(&g_cnt2, 1u) == NGROUPS - 1u);
    }
    __syncthreads();
    if (!s_last) return;
    if (tid == 0) __threadfence();
    __syncthreads();

    {
        float gm = g_m2[0];
        #pragma unroll
        for (int j = 1; j < NGROUPS; ++j) gm = fmaxf(gm, g_m2[j]);

        float acc = 0.0f;
        float ll  = 0.0f;
        #pragma unroll 4
        for (int j = 0; j < NGROUPS; ++j) {
            const float sf = __expf(g_m2[j] - gm);
            acc += g_part2[j][tid] * sf;
            ll  += g_l2[j] * sf;
        }
        out[tid] = acc / ll;
    }

    // Reset counters for next graph replay (only this CTA is alive here).
    if (tid < NGROUPS) g_cnt1[tid] = 0u;
    if (tid == 0) g_cnt2 = 0u;
}

extern "C" void kernel_launch(void* const* d_in, const int* in_sizes, int n_in,
                              void* d_out, int out_size) {
    const float* q = (const float*)d_in[0];
    const float* K = (const float*)d_in[1];
    const float* V = (const float*)d_in[2];
    float* out = (float*)d_out;

    sqa_fused<<<NUM_CTAS, 256>>>(q, K, V, out);
}